// round 13
// baseline (speedup 1.0000x reference)
#include <cuda_runtime.h>
#include <cuda_bf16.h>
#include <math.h>
#include <stdint.h>

// Problem constants
#define BB     4
#define CIN    256
#define HS     64
#define SFULL  512
#define CC     8
#define SMDIM  128
#define KP     4
#define PP     8
#define LL     256          // K of matmul
#define QQ     4096         // M total per (b,c)
#define PSQ    64           // N of matmul
#define OUT_ELEMS  (BB*CC*SFULL*SFULL)

// -------- scratch (device globals) --------
__device__ float g_y64[BB*CC*HS*HS];
__device__ __nv_bfloat16 g_Ub[BB*CC*PSQ*LL];            // [bc][p=64][k=256] bf16

__device__ __forceinline__ uint32_t smem_u32(const void* p) {
    uint32_t a;
    asm("{ .reg .u64 t; cvta.to.shared.u64 t, %1; cvt.u32.u64 %0, t; }"
        : "=r"(a) : "l"(p));
    return a;
}
#define CP16(dst_u32, src) \
    asm volatile("cp.async.cg.shared.global [%0], [%1], 16;" \
                 :: "r"(dst_u32), "l"(src))
#define CP_COMMIT() asm volatile("cp.async.commit_group;")
#define CP_WAIT1()  asm volatile("cp.async.wait_group 1;")

// ================= Kernel A: 1x1 conv (256 -> 8), 32px x 8 ic-split =================
// All 32 loads issued as ONE batch (single DRAM-latency exposure per thread).
__global__ void __launch_bounds__(256)
conv1x1_kernel(const float* __restrict__ x,
               const float* __restrict__ w,
               const float* __restrict__ b) {
    __shared__ float ws[CC*CIN];
    __shared__ float sacc[32*9];
    int tid = threadIdx.x;
    for (int i = tid; i < CC*CIN; i += 256) ws[i] = w[i];
    if (tid < 144) { sacc[tid] = 0.f; sacc[tid + 144] = 0.f; }
    __syncthreads();

    int px  = tid & 31;
    int icq = tid >> 5;                    // 0..7, 32 ic each
    int pid = blockIdx.x*32 + px;
    int bb  = pid >> 12;
    int p   = pid & 4095;

    const float* xp = x + (size_t)bb*CIN*HS*HS + (size_t)icq*32*HS*HS + p;

    float xv[32];
#pragma unroll
    for (int j = 0; j < 32; ++j)
        xv[j] = xp[(size_t)j*HS*HS];       // 32 independent LDGs, front-batched

    float acc[CC];
#pragma unroll
    for (int c = 0; c < CC; ++c) acc[c] = 0.f;
#pragma unroll
    for (int j = 0; j < 32; ++j) {
        int icg = icq*32 + j;
#pragma unroll
        for (int c = 0; c < CC; ++c) acc[c] += xv[j] * ws[c*CIN + icg];
    }
#pragma unroll
    for (int c = 0; c < CC; ++c) atomicAdd(&sacc[px*9 + c], acc[c]);
    __syncthreads();

    if (tid < 32) {
        int pid2 = blockIdx.x*32 + tid;
        int bb2  = pid2 >> 12;
        int p2   = pid2 & 4095;
#pragma unroll
        for (int c = 0; c < CC; ++c)
            g_y64[(bb2*CC + c)*HS*HS + p2] = sacc[tid*9 + c] + b[c];
    }
}

// ========= Kernel B: bilinear->argmax->4x4 pool -> unfold (bf16, [p][k]) =========
__global__ void argmax_pool_kernel() {
    int idx = blockIdx.x * blockDim.x + threadIdx.x;
    if (idx >= BB*SMDIM*SMDIM) return;
    int bb = idx >> 14;
    int r  = idx & 16383;
    int u  = r >> 7;
    int v  = r & 127;

    const double sc = 63.0 / 511.0;
    int cnt[CC];
#pragma unroll
    for (int c = 0; c < CC; ++c) cnt[c] = 0;

    const float* yb = g_y64 + bb*CC*HS*HS;

#pragma unroll
    for (int i = 0; i < KP; ++i) {
        int s = u*KP + i;
        float ps = (float)(s * sc);
        int lo_s = (int)ps; if (lo_s > 63) lo_s = 63;
        float wsv = ps - (float)lo_s;
        int hi_s = lo_s + 1; if (hi_s > 63) hi_s = 63;
#pragma unroll
        for (int j = 0; j < KP; ++j) {
            int t = v*KP + j;
            float pt = (float)(t * sc);
            int lo_t = (int)pt; if (lo_t > 63) lo_t = 63;
            float wtv = pt - (float)lo_t;
            int hi_t = lo_t + 1; if (hi_t > 63) hi_t = 63;

            float w00 = (1.f-wsv)*(1.f-wtv);
            float w01 = (1.f-wsv)*wtv;
            float w10 = wsv*(1.f-wtv);
            float w11 = wsv*wtv;

            float best = -3.4e38f;
            int bi = 0;
#pragma unroll
            for (int c = 0; c < CC; ++c) {
                const float* yc = yb + c*HS*HS;
                float yv = w00*yc[lo_s*HS + lo_t] + w01*yc[lo_s*HS + hi_t]
                         + w10*yc[hi_s*HS + lo_t] + w11*yc[hi_s*HS + hi_t];
                if (yv > best) { best = yv; bi = c; }
            }
            cnt[bi]++;
        }
    }

    int p = ((u & 7) << 3) | (v & 7);
    int l = ((u >> 3) << 4) | (v >> 3);
#pragma unroll
    for (int c = 0; c < CC; ++c)
        g_Ub[((bb*CC + c)*PSQ + p)*LL + l] =
            __float2bfloat16((float)cnt[c] * 0.0625f);
}

// ====== Kernel D: fused GEMM(8 classes) + nz + passthrough + softmax, cp.async pipelined ======
#define ALD 264
#define OFF_AS    0
#define OFF_BS    16896                    // 32*ALD*2
#define OFF_STAGE 50688                    // + 64*ALD*2
#define OFF_YROW  83456                    // + 2*16*256*4
#define FUSED_SMEM 99840                   // + 4096*4

__global__ void __launch_bounds__(256, 2)
fused_kernel(const float* __restrict__ attn, float* __restrict__ out,
             float* __restrict__ attn_out) {
    extern __shared__ char dsm[];
    __nv_bfloat16* As = (__nv_bfloat16*)(dsm + OFF_AS);     // [32][ALD]
    __nv_bfloat16* Bs = (__nv_bfloat16*)(dsm + OFF_BS);     // [64][ALD]
    float* stagef     = (float*)(dsm + OFF_STAGE);          // [2][16*256]
    float* yrow       = (float*)(dsm + OFF_YROW);           // [8c][8sr][64]
    __shared__ float scales[CC][32];
    __shared__ int   cnts[CC][32];

    const int tid  = threadIdx.x;
    const int wid  = tid >> 5, lane = tid & 31;
    const int g    = lane >> 2, tg = lane & 3;
    const int wr   = wid & 1,  wc  = wid >> 1;
    const int mrow = wr * 16;
    const int mt   = blockIdx.x;
    const int b    = blockIdx.y;
    const int m0   = mt * 32;
    const int sh0  = (mt >> 1) * 8;
    const double sc = 63.0 / 511.0;

    ((int*)cnts)[tid] = 0;                 // 256 ints exactly

    const uint32_t stage_u32 = smem_u32(stagef);
    const uint32_t bs_u32    = smem_u32(Bs);

    // ---- prologue: G0 = A(c0,h0)+B(c0); G1 = A(c0,h1) ----
    {
        const char* a0 = (const char*)(attn + ((size_t)(b*CC+0)*QQ + m0)*LL);
        const char* bsrc = (const char*)(g_Ub + (size_t)(b*CC+0)*PSQ*LL);
#pragma unroll
        for (int i = 0; i < 4; ++i) {
            int ch = i*256 + tid;
            CP16(stage_u32 + ch*16, a0 + ch*16);
        }
#pragma unroll
        for (int i = 0; i < 8; ++i) {
            int ch = i*256 + tid;
            CP16(bs_u32 + (ch >> 5)*528 + (ch & 31)*16, bsrc + ch*16);
        }
        CP_COMMIT();
#pragma unroll
        for (int i = 0; i < 4; ++i) {
            int ch = i*256 + tid;
            CP16(stage_u32 + 16384 + ch*16, a0 + 16384 + ch*16);
        }
        CP_COMMIT();
    }

    // ---- yrow precompute (overlaps prologue cp.async latency) ----
#pragma unroll
    for (int it = 0; it < 16; ++it) {
        int i   = it*256 + tid;
        int c   = i >> 9;
        int sr  = (i >> 6) & 7;
        int col = i & 63;
        int s   = sh0 + sr;
        float ps = (float)(s * sc);
        int ls = (int)ps; if (ls > 63) ls = 63;
        float wsv = ps - (float)ls;
        int hs = ls + 1; if (hs > 63) hs = 63;
        const float* yc = g_y64 + (b*CC + c)*HS*HS;
        float lo = yc[ls*HS + col], hi = yc[hs*HS + col];
        yrow[i] = lo + wsv*(hi - lo);
    }

    float corr[CC][2][4];
#pragma unroll
    for (int c = 0; c < CC; ++c)
#pragma unroll
        for (int j = 0; j < 2; ++j)
#pragma unroll
            for (int i = 0; i < 4; ++i) corr[c][j][i] = 0.f;

    // ---- pipelined stage loop: 16 stages = 8 classes x 2 half-tiles ----
#pragma unroll
    for (int s = 0; s < 16; ++s) {
        const int c = s >> 1, h = s & 1;
        const int bc = b*CC + c;

        CP_WAIT1();
        __syncthreads();                   // stage s data visible; prev readers done

        // process stage s: passthrough (.cs) + nz + bf16 -> As
        float4* Og  = (float4*)(attn_out + ((size_t)bc*QQ + m0)*LL);
        const float4* buf = (const float4*)(stagef + (s & 1)*4096);
#pragma unroll
        for (int i = 0; i < 4; ++i) {
            int flat = i*256 + tid;        // float4 idx within half
            int row  = h*16 + (flat >> 6); // warp-uniform
            int k    = (flat & 63) << 2;
            float4 v = buf[flat];
            __stcs(&Og[h*1024 + flat], v);
            int cn = (v.x != 0.f) + (v.y != 0.f) + (v.z != 0.f) + (v.w != 0.f);
            cn = __reduce_add_sync(0xFFFFFFFFu, cn);
            if (lane == 0) atomicAdd(&cnts[c][row], cn);
            __nv_bfloat162 h0 = __floats2bfloat162_rn(v.x, v.y);
            __nv_bfloat162 h1 = __floats2bfloat162_rn(v.z, v.w);
            *(uint2*)(As + row*ALD + k) = make_uint2(*(uint32_t*)&h0, *(uint32_t*)&h1);
        }
        __syncthreads();                   // buf[s&1] free; As half done

        if (h == 0) {
            // prefetch stage s+2 = (class c+1, half0)
            if (s + 2 <= 15) {
                int c2 = (s+2) >> 1;
                const char* asrc = (const char*)(attn +
                    ((size_t)(b*CC+c2)*QQ + m0)*LL);
#pragma unroll
                for (int i = 0; i < 4; ++i) {
                    int ch = i*256 + tid;
                    CP16(stage_u32 + (s & 1)*16384 + ch*16, asrc + ch*16);
                }
            }
            CP_COMMIT();
        } else {
            // EARLY prefetch of A(c+1, half1): slot free, MMA gives latency cover.
            if (s + 2 <= 15) {
                int c2 = (s+2) >> 1;
                const char* asrc = (const char*)(attn +
                    ((size_t)(b*CC+c2)*QQ + m0 + 16)*LL);   // half1 rows
#pragma unroll
                for (int i = 0; i < 4; ++i) {
                    int ch = i*256 + tid;
                    CP16(stage_u32 + (s & 1)*16384 + ch*16, asrc + ch*16);
                }
            }
            CP_COMMIT();

            if (tid < 32) scales[c][tid] = 1.f / ((float)cnts[c][tid] + 1e-5f);
            __syncthreads();               // scales + full As visible

            // HMMA for class c
            const __nv_bfloat16* Ab = As + (mrow + g)*ALD + tg*2;
#pragma unroll 4
            for (int ks = 0; ks < 16; ++ks) {
                int kk = ks * 16;
                uint32_t a0 = *(const uint32_t*)(Ab + kk);
                uint32_t a1 = *(const uint32_t*)(Ab + 8*ALD + kk);
                uint32_t a2 = *(const uint32_t*)(Ab + kk + 8);
                uint32_t a3 = *(const uint32_t*)(Ab + 8*ALD + kk + 8);
#pragma unroll
                for (int j = 0; j < 2; ++j) {
                    const __nv_bfloat16* Bb = Bs + (wc*16 + j*8 + g)*ALD + kk + tg*2;
                    uint32_t b0 = *(const uint32_t*)(Bb);
                    uint32_t b1 = *(const uint32_t*)(Bb + 8);
                    asm volatile(
                        "mma.sync.aligned.m16n8k16.row.col.f32.bf16.bf16.f32 "
                        "{%0,%1,%2,%3}, {%4,%5,%6,%7}, {%8,%9}, {%0,%1,%2,%3};"
                        : "+f"(corr[c][j][0]), "+f"(corr[c][j][1]),
                          "+f"(corr[c][j][2]), "+f"(corr[c][j][3])
                        : "r"(a0), "r"(a1), "r"(a2), "r"(a3), "r"(b0), "r"(b1));
                }
            }
            float s0 = scales[c][mrow + g];
            float s1 = scales[c][mrow + g + 8];
#pragma unroll
            for (int j = 0; j < 2; ++j) {
                corr[c][j][0] *= s0; corr[c][j][1] *= s0;
                corr[c][j][2] *= s1; corr[c][j][3] *= s1;
            }
            __syncthreads();               // all MMA reads of As/Bs done

            // B(c+1) prefetch (Bs single-buffered -> must follow MMA)
            if (s + 2 <= 15) {
                int c2 = (s+2) >> 1;
                const char* bsrc = (const char*)(g_Ub + (size_t)(b*CC+c2)*PSQ*LL);
#pragma unroll
                for (int i = 0; i < 8; ++i) {
                    int ch = i*256 + tid;
                    CP16(bs_u32 + (ch >> 5)*528 + (ch & 31)*16, bsrc + ch*16);
                }
            }
            CP_COMMIT();
        }
    }

    // ---- fused epilogue: (corr+1)*y, log_softmax, write out (.cs) ----
#pragma unroll
    for (int r = 0; r < 2; ++r) {
        int qrow = mrow + g + r*8;
        int q    = m0 + qrow;
        int t0   = ((q & 63) << 3) + tg*2;
        int t1   = t0 + 1;
        float pt0 = (float)(t0 * sc);
        int lt0 = (int)pt0; if (lt0 > 63) lt0 = 63;
        float wt0 = pt0 - (float)lt0;
        int ht0 = lt0 + 1; if (ht0 > 63) ht0 = 63;
        float pt1 = (float)(t1 * sc);
        int lt1 = (int)pt1; if (lt1 > 63) lt1 = 63;
        float wt1 = pt1 - (float)lt1;
        int ht1 = lt1 + 1; if (ht1 > 63) ht1 = 63;

#pragma unroll
        for (int j = 0; j < 2; ++j) {
            int sr = wc*2 + j;
            float v0[CC], v1[CC];
            float m0v = -3.4e38f, m1v = -3.4e38f;
#pragma unroll
            for (int c = 0; c < CC; ++c) {
                const float* yr = yrow + (c*8 + sr)*64;
                float a0 = yr[lt0];
                float y0 = a0 + wt0*(yr[ht0] - a0);
                float a1 = yr[lt1];
                float y1 = a1 + wt1*(yr[ht1] - a1);
                v0[c] = (corr[c][j][r*2+0] + 1.f) * y0;
                v1[c] = (corr[c][j][r*2+1] + 1.f) * y1;
                m0v = fmaxf(m0v, v0[c]);
                m1v = fmaxf(m1v, v1[c]);
            }
            float su0 = 0.f, su1 = 0.f;
#pragma unroll
            for (int c = 0; c < CC; ++c) {
                su0 += __expf(v0[c] - m0v);
                su1 += __expf(v1[c] - m1v);
            }
            float lse0 = logf(su0) + m0v;
            float lse1 = logf(su1) + m1v;
            int s_glob = sh0 + sr;
#pragma unroll
            for (int c = 0; c < CC; ++c) {
                float* op = out + (((size_t)(b*CC + c)) << 18) + (s_glob << 9) + t0;
                __stcs((float2*)op, make_float2(v0[c] - lse0, v1[c] - lse1));
            }
        }
    }
}

// ======================= launch =======================
extern "C" void kernel_launch(void* const* d_in, const int* in_sizes, int n_in,
                              void* d_out, int out_size) {
    const float* x    = (const float*)d_in[0];
    const float* attn = (const float*)d_in[1];
    const float* cw   = (const float*)d_in[2];
    const float* cb   = (const float*)d_in[3];
    float* out = (float*)d_out;

    conv1x1_kernel<<<BB*HS*HS/32, 256>>>(x, cw, cb);
    argmax_pool_kernel<<<(BB*SMDIM*SMDIM + 255)/256, 256>>>();

    static int smem_set = 0;
    if (!smem_set) {
        cudaFuncSetAttribute(fused_kernel,
                             cudaFuncAttributeMaxDynamicSharedMemorySize,
                             FUSED_SMEM);
        smem_set = 1;
    }
    fused_kernel<<<dim3(QQ/32, BB), 256, FUSED_SMEM>>>(attn, out, out + OUT_ELEMS);
}

// round 14
// speedup vs baseline: 1.0003x; 1.0003x over previous
#include <cuda_runtime.h>
#include <cuda_bf16.h>
#include <math.h>
#include <stdint.h>

// Problem constants
#define BB     4
#define CIN    256
#define HS     64
#define SFULL  512
#define CC     8
#define SMDIM  128
#define KP     4
#define PP     8
#define LL     256          // K of matmul
#define QQ     4096         // M total per (b,c)
#define PSQ    64           // N of matmul
#define OUT_ELEMS  (BB*CC*SFULL*SFULL)

// -------- scratch (device globals) --------
__device__ float g_y64[BB*CC*HS*HS];
__device__ __nv_bfloat16 g_Ub[BB*CC*PSQ*LL];            // [bc][p=64][k=256] bf16

__device__ __forceinline__ uint32_t smem_u32(const void* p) {
    uint32_t a;
    asm("{ .reg .u64 t; cvta.to.shared.u64 t, %1; cvt.u32.u64 %0, t; }"
        : "=r"(a) : "l"(p));
    return a;
}
#define CP16(dst_u32, src) \
    asm volatile("cp.async.cg.shared.global [%0], [%1], 16;" \
                 :: "r"(dst_u32), "l"(src))
#define CP_COMMIT() asm volatile("cp.async.commit_group;")
#define CP_WAIT1()  asm volatile("cp.async.wait_group 1;")

// ================= Kernel A: 1x1 conv (256 -> 8), 32px x 8 ic-split =================
// All 32 loads emitted inside ONE asm volatile block: ptxas cannot split the
// batch -> guaranteed 32 loads in flight per thread (single latency exposure).
__global__ void __launch_bounds__(256)
conv1x1_kernel(const float* __restrict__ x,
               const float* __restrict__ w,
               const float* __restrict__ b) {
    __shared__ float ws[CC*CIN];
    __shared__ float sacc[32*9];
    int tid = threadIdx.x;
    for (int i = tid; i < CC*CIN; i += 256) ws[i] = w[i];
    if (tid < 144) { sacc[tid] = 0.f; sacc[tid + 144] = 0.f; }
    __syncthreads();

    int px  = tid & 31;
    int icq = tid >> 5;                    // 0..7, 32 ic each
    int pid = blockIdx.x*32 + px;
    int bb  = pid >> 12;
    int p   = pid & 4095;

    const float* xp = x + (size_t)bb*CIN*HS*HS + (size_t)icq*32*HS*HS + p;

    float xv[32];
    asm volatile(
        "ld.global.nc.f32 %0,  [%32];\n\t"
        "ld.global.nc.f32 %1,  [%32+16384];\n\t"
        "ld.global.nc.f32 %2,  [%32+32768];\n\t"
        "ld.global.nc.f32 %3,  [%32+49152];\n\t"
        "ld.global.nc.f32 %4,  [%32+65536];\n\t"
        "ld.global.nc.f32 %5,  [%32+81920];\n\t"
        "ld.global.nc.f32 %6,  [%32+98304];\n\t"
        "ld.global.nc.f32 %7,  [%32+114688];\n\t"
        "ld.global.nc.f32 %8,  [%32+131072];\n\t"
        "ld.global.nc.f32 %9,  [%32+147456];\n\t"
        "ld.global.nc.f32 %10, [%32+163840];\n\t"
        "ld.global.nc.f32 %11, [%32+180224];\n\t"
        "ld.global.nc.f32 %12, [%32+196608];\n\t"
        "ld.global.nc.f32 %13, [%32+212992];\n\t"
        "ld.global.nc.f32 %14, [%32+229376];\n\t"
        "ld.global.nc.f32 %15, [%32+245760];\n\t"
        "ld.global.nc.f32 %16, [%32+262144];\n\t"
        "ld.global.nc.f32 %17, [%32+278528];\n\t"
        "ld.global.nc.f32 %18, [%32+294912];\n\t"
        "ld.global.nc.f32 %19, [%32+311296];\n\t"
        "ld.global.nc.f32 %20, [%32+327680];\n\t"
        "ld.global.nc.f32 %21, [%32+344064];\n\t"
        "ld.global.nc.f32 %22, [%32+360448];\n\t"
        "ld.global.nc.f32 %23, [%32+376832];\n\t"
        "ld.global.nc.f32 %24, [%32+393216];\n\t"
        "ld.global.nc.f32 %25, [%32+409600];\n\t"
        "ld.global.nc.f32 %26, [%32+425984];\n\t"
        "ld.global.nc.f32 %27, [%32+442368];\n\t"
        "ld.global.nc.f32 %28, [%32+458752];\n\t"
        "ld.global.nc.f32 %29, [%32+475136];\n\t"
        "ld.global.nc.f32 %30, [%32+491520];\n\t"
        "ld.global.nc.f32 %31, [%32+507904];"
        : "=f"(xv[0]), "=f"(xv[1]), "=f"(xv[2]), "=f"(xv[3]),
          "=f"(xv[4]), "=f"(xv[5]), "=f"(xv[6]), "=f"(xv[7]),
          "=f"(xv[8]), "=f"(xv[9]), "=f"(xv[10]), "=f"(xv[11]),
          "=f"(xv[12]), "=f"(xv[13]), "=f"(xv[14]), "=f"(xv[15]),
          "=f"(xv[16]), "=f"(xv[17]), "=f"(xv[18]), "=f"(xv[19]),
          "=f"(xv[20]), "=f"(xv[21]), "=f"(xv[22]), "=f"(xv[23]),
          "=f"(xv[24]), "=f"(xv[25]), "=f"(xv[26]), "=f"(xv[27]),
          "=f"(xv[28]), "=f"(xv[29]), "=f"(xv[30]), "=f"(xv[31])
        : "l"(xp));

    float acc[CC];
#pragma unroll
    for (int c = 0; c < CC; ++c) acc[c] = 0.f;
#pragma unroll
    for (int j = 0; j < 32; ++j) {
        int icg = icq*32 + j;
#pragma unroll
        for (int c = 0; c < CC; ++c) acc[c] += xv[j] * ws[c*CIN + icg];
    }
#pragma unroll
    for (int c = 0; c < CC; ++c) atomicAdd(&sacc[px*9 + c], acc[c]);
    __syncthreads();

    if (tid < 32) {
        int pid2 = blockIdx.x*32 + tid;
        int bb2  = pid2 >> 12;
        int p2   = pid2 & 4095;
#pragma unroll
        for (int c = 0; c < CC; ++c)
            g_y64[(bb2*CC + c)*HS*HS + p2] = sacc[tid*9 + c] + b[c];
    }
}

// ========= Kernel B: bilinear->argmax->4x4 pool -> unfold (bf16, [p][k]) =========
__global__ void argmax_pool_kernel() {
    int idx = blockIdx.x * blockDim.x + threadIdx.x;
    if (idx >= BB*SMDIM*SMDIM) return;
    int bb = idx >> 14;
    int r  = idx & 16383;
    int u  = r >> 7;
    int v  = r & 127;

    const double sc = 63.0 / 511.0;
    int cnt[CC];
#pragma unroll
    for (int c = 0; c < CC; ++c) cnt[c] = 0;

    const float* yb = g_y64 + bb*CC*HS*HS;

#pragma unroll
    for (int i = 0; i < KP; ++i) {
        int s = u*KP + i;
        float ps = (float)(s * sc);
        int lo_s = (int)ps; if (lo_s > 63) lo_s = 63;
        float wsv = ps - (float)lo_s;
        int hi_s = lo_s + 1; if (hi_s > 63) hi_s = 63;
#pragma unroll
        for (int j = 0; j < KP; ++j) {
            int t = v*KP + j;
            float pt = (float)(t * sc);
            int lo_t = (int)pt; if (lo_t > 63) lo_t = 63;
            float wtv = pt - (float)lo_t;
            int hi_t = lo_t + 1; if (hi_t > 63) hi_t = 63;

            float w00 = (1.f-wsv)*(1.f-wtv);
            float w01 = (1.f-wsv)*wtv;
            float w10 = wsv*(1.f-wtv);
            float w11 = wsv*wtv;

            float best = -3.4e38f;
            int bi = 0;
#pragma unroll
            for (int c = 0; c < CC; ++c) {
                const float* yc = yb + c*HS*HS;
                float yv = w00*yc[lo_s*HS + lo_t] + w01*yc[lo_s*HS + hi_t]
                         + w10*yc[hi_s*HS + lo_t] + w11*yc[hi_s*HS + hi_t];
                if (yv > best) { best = yv; bi = c; }
            }
            cnt[bi]++;
        }
    }

    int p = ((u & 7) << 3) | (v & 7);
    int l = ((u >> 3) << 4) | (v >> 3);
#pragma unroll
    for (int c = 0; c < CC; ++c)
        g_Ub[((bb*CC + c)*PSQ + p)*LL + l] =
            __float2bfloat16((float)cnt[c] * 0.0625f);
}

// ====== Kernel D: fused GEMM(8 classes) + nz + passthrough + softmax, cp.async pipelined ======
#define ALD 264
#define OFF_AS    0
#define OFF_BS    16896                    // 32*ALD*2
#define OFF_STAGE 50688                    // + 64*ALD*2
#define OFF_YROW  83456                    // + 2*16*256*4
#define FUSED_SMEM 99840                   // + 4096*4

__global__ void __launch_bounds__(256, 2)
fused_kernel(const float* __restrict__ attn, float* __restrict__ out,
             float* __restrict__ attn_out) {
    extern __shared__ char dsm[];
    __nv_bfloat16* As = (__nv_bfloat16*)(dsm + OFF_AS);     // [32][ALD]
    __nv_bfloat16* Bs = (__nv_bfloat16*)(dsm + OFF_BS);     // [64][ALD]
    float* stagef     = (float*)(dsm + OFF_STAGE);          // [2][16*256]
    float* yrow       = (float*)(dsm + OFF_YROW);           // [8c][8sr][64]
    __shared__ int   cnts[CC][32];

    const int tid  = threadIdx.x;
    const int wid  = tid >> 5, lane = tid & 31;
    const int g    = lane >> 2, tg = lane & 3;
    const int wr   = wid & 1,  wc  = wid >> 1;
    const int mrow = wr * 16;
    const int mt   = blockIdx.x;
    const int b    = blockIdx.y;
    const int m0   = mt * 32;
    const int sh0  = (mt >> 1) * 8;
    const double sc = 63.0 / 511.0;

    ((int*)cnts)[tid] = 0;                 // 256 ints exactly

    const uint32_t stage_u32 = smem_u32(stagef);
    const uint32_t bs_u32    = smem_u32(Bs);

    // ---- prologue: G0 = A(c0,h0)+B(c0); G1 = A(c0,h1) ----
    {
        const char* a0 = (const char*)(attn + ((size_t)(b*CC+0)*QQ + m0)*LL);
        const char* bsrc = (const char*)(g_Ub + (size_t)(b*CC+0)*PSQ*LL);
#pragma unroll
        for (int i = 0; i < 4; ++i) {
            int ch = i*256 + tid;
            CP16(stage_u32 + ch*16, a0 + ch*16);
        }
#pragma unroll
        for (int i = 0; i < 8; ++i) {
            int ch = i*256 + tid;
            CP16(bs_u32 + (ch >> 5)*528 + (ch & 31)*16, bsrc + ch*16);
        }
        CP_COMMIT();
#pragma unroll
        for (int i = 0; i < 4; ++i) {
            int ch = i*256 + tid;
            CP16(stage_u32 + 16384 + ch*16, a0 + 16384 + ch*16);
        }
        CP_COMMIT();
    }

    // ---- yrow precompute (overlaps prologue cp.async latency) ----
#pragma unroll
    for (int it = 0; it < 16; ++it) {
        int i   = it*256 + tid;
        int c   = i >> 9;
        int sr  = (i >> 6) & 7;
        int col = i & 63;
        int s   = sh0 + sr;
        float ps = (float)(s * sc);
        int ls = (int)ps; if (ls > 63) ls = 63;
        float wsv = ps - (float)ls;
        int hs = ls + 1; if (hs > 63) hs = 63;
        const float* yc = g_y64 + (b*CC + c)*HS*HS;
        float lo = yc[ls*HS + col], hi = yc[hs*HS + col];
        yrow[i] = lo + wsv*(hi - lo);
    }

    float corr[CC][2][4];
#pragma unroll
    for (int c = 0; c < CC; ++c)
#pragma unroll
        for (int j = 0; j < 2; ++j)
#pragma unroll
            for (int i = 0; i < 4; ++i) corr[c][j][i] = 0.f;

    // ---- pipelined stage loop: 16 stages = 8 classes x 2 half-tiles ----
#pragma unroll
    for (int s = 0; s < 16; ++s) {
        const int c = s >> 1, h = s & 1;
        const int bc = b*CC + c;

        CP_WAIT1();
        __syncthreads();                   // stage s data visible; prev readers done

        // process stage s: passthrough (.cs) + nz + bf16 -> As
        float4* Og  = (float4*)(attn_out + ((size_t)bc*QQ + m0)*LL);
        const float4* buf = (const float4*)(stagef + (s & 1)*4096);
#pragma unroll
        for (int i = 0; i < 4; ++i) {
            int flat = i*256 + tid;        // float4 idx within half
            int row  = h*16 + (flat >> 6); // warp-uniform
            int k    = (flat & 63) << 2;
            float4 v = buf[flat];
            __stcs(&Og[h*1024 + flat], v);
            int cn = (v.x != 0.f) + (v.y != 0.f) + (v.z != 0.f) + (v.w != 0.f);
            cn = __reduce_add_sync(0xFFFFFFFFu, cn);
            if (lane == 0) atomicAdd(&cnts[c][row], cn);
            __nv_bfloat162 h0 = __floats2bfloat162_rn(v.x, v.y);
            __nv_bfloat162 h1 = __floats2bfloat162_rn(v.z, v.w);
            *(uint2*)(As + row*ALD + k) = make_uint2(*(uint32_t*)&h0, *(uint32_t*)&h1);
        }
        __syncthreads();                   // buf[s&1] free; As half + cnts done

        if (h == 0) {
            // prefetch stage s+2 = (class c+1, half0)
            if (s + 2 <= 15) {
                int c2 = (s+2) >> 1;
                const char* asrc = (const char*)(attn +
                    ((size_t)(b*CC+c2)*QQ + m0)*LL);
#pragma unroll
                for (int i = 0; i < 4; ++i) {
                    int ch = i*256 + tid;
                    CP16(stage_u32 + (s & 1)*16384 + ch*16, asrc + ch*16);
                }
            }
            CP_COMMIT();
        } else {
            // EARLY prefetch of A(c+1, half1): slot free, MMA gives latency cover.
            if (s + 2 <= 15) {
                int c2 = (s+2) >> 1;
                const char* asrc = (const char*)(attn +
                    ((size_t)(b*CC+c2)*QQ + m0 + 16)*LL);   // half1 rows
#pragma unroll
                for (int i = 0; i < 4; ++i) {
                    int ch = i*256 + tid;
                    CP16(stage_u32 + (s & 1)*16384 + ch*16, asrc + ch*16);
                }
            }
            CP_COMMIT();

            // per-thread row scales straight from cnts (post-processing sync
            // already made cnts + both As halves visible) — no extra barrier.
            float s0 = 1.f / ((float)cnts[c][mrow + g] + 1e-5f);
            float s1 = 1.f / ((float)cnts[c][mrow + g + 8] + 1e-5f);

            // HMMA for class c
            const __nv_bfloat16* Ab = As + (mrow + g)*ALD + tg*2;
#pragma unroll 4
            for (int ks = 0; ks < 16; ++ks) {
                int kk = ks * 16;
                uint32_t a0 = *(const uint32_t*)(Ab + kk);
                uint32_t a1 = *(const uint32_t*)(Ab + 8*ALD + kk);
                uint32_t a2 = *(const uint32_t*)(Ab + kk + 8);
                uint32_t a3 = *(const uint32_t*)(Ab + 8*ALD + kk + 8);
#pragma unroll
                for (int j = 0; j < 2; ++j) {
                    const __nv_bfloat16* Bb = Bs + (wc*16 + j*8 + g)*ALD + kk + tg*2;
                    uint32_t b0 = *(const uint32_t*)(Bb);
                    uint32_t b1 = *(const uint32_t*)(Bb + 8);
                    asm volatile(
                        "mma.sync.aligned.m16n8k16.row.col.f32.bf16.bf16.f32 "
                        "{%0,%1,%2,%3}, {%4,%5,%6,%7}, {%8,%9}, {%0,%1,%2,%3};"
                        : "+f"(corr[c][j][0]), "+f"(corr[c][j][1]),
                          "+f"(corr[c][j][2]), "+f"(corr[c][j][3])
                        : "r"(a0), "r"(a1), "r"(a2), "r"(a3), "r"(b0), "r"(b1));
                }
            }
#pragma unroll
            for (int j = 0; j < 2; ++j) {
                corr[c][j][0] *= s0; corr[c][j][1] *= s0;
                corr[c][j][2] *= s1; corr[c][j][3] *= s1;
            }
            __syncthreads();               // all MMA reads of As/Bs done

            // B(c+1) prefetch (Bs single-buffered -> must follow MMA)
            if (s + 2 <= 15) {
                int c2 = (s+2) >> 1;
                const char* bsrc = (const char*)(g_Ub + (size_t)(b*CC+c2)*PSQ*LL);
#pragma unroll
                for (int i = 0; i < 8; ++i) {
                    int ch = i*256 + tid;
                    CP16(bs_u32 + (ch >> 5)*528 + (ch & 31)*16, bsrc + ch*16);
                }
            }
            CP_COMMIT();
        }
    }

    // ---- fused epilogue: (corr+1)*y, log_softmax, write out (.cs) ----
#pragma unroll
    for (int r = 0; r < 2; ++r) {
        int qrow = mrow + g + r*8;
        int q    = m0 + qrow;
        int t0   = ((q & 63) << 3) + tg*2;
        int t1   = t0 + 1;
        float pt0 = (float)(t0 * sc);
        int lt0 = (int)pt0; if (lt0 > 63) lt0 = 63;
        float wt0 = pt0 - (float)lt0;
        int ht0 = lt0 + 1; if (ht0 > 63) ht0 = 63;
        float pt1 = (float)(t1 * sc);
        int lt1 = (int)pt1; if (lt1 > 63) lt1 = 63;
        float wt1 = pt1 - (float)lt1;
        int ht1 = lt1 + 1; if (ht1 > 63) ht1 = 63;

#pragma unroll
        for (int j = 0; j < 2; ++j) {
            int sr = wc*2 + j;
            float v0[CC], v1[CC];
            float m0v = -3.4e38f, m1v = -3.4e38f;
#pragma unroll
            for (int c = 0; c < CC; ++c) {
                const float* yr = yrow + (c*8 + sr)*64;
                float a0 = yr[lt0];
                float y0 = a0 + wt0*(yr[ht0] - a0);
                float a1 = yr[lt1];
                float y1 = a1 + wt1*(yr[ht1] - a1);
                v0[c] = (corr[c][j][r*2+0] + 1.f) * y0;
                v1[c] = (corr[c][j][r*2+1] + 1.f) * y1;
                m0v = fmaxf(m0v, v0[c]);
                m1v = fmaxf(m1v, v1[c]);
            }
            float su0 = 0.f, su1 = 0.f;
#pragma unroll
            for (int c = 0; c < CC; ++c) {
                su0 += __expf(v0[c] - m0v);
                su1 += __expf(v1[c] - m1v);
            }
            float lse0 = logf(su0) + m0v;
            float lse1 = logf(su1) + m1v;
            int s_glob = sh0 + sr;
#pragma unroll
            for (int c = 0; c < CC; ++c) {
                float* op = out + (((size_t)(b*CC + c)) << 18) + (s_glob << 9) + t0;
                __stcs((float2*)op, make_float2(v0[c] - lse0, v1[c] - lse1));
            }
        }
    }
}

// ======================= launch =======================
extern "C" void kernel_launch(void* const* d_in, const int* in_sizes, int n_in,
                              void* d_out, int out_size) {
    const float* x    = (const float*)d_in[0];
    const float* attn = (const float*)d_in[1];
    const float* cw   = (const float*)d_in[2];
    const float* cb   = (const float*)d_in[3];
    float* out = (float*)d_out;

    conv1x1_kernel<<<BB*HS*HS/32, 256>>>(x, cw, cb);
    argmax_pool_kernel<<<(BB*SMDIM*SMDIM + 255)/256, 256>>>();

    static int smem_set = 0;
    if (!smem_set) {
        cudaFuncSetAttribute(fused_kernel,
                             cudaFuncAttributeMaxDynamicSharedMemorySize,
                             FUSED_SMEM);
        smem_set = 1;
    }
    fused_kernel<<<dim3(QQ/32, BB), 256, FUSED_SMEM>>>(attn, out, out + OUT_ELEMS);
}

// round 17
// speedup vs baseline: 1.0238x; 1.0235x over previous
#include <cuda_runtime.h>
#include <cuda_bf16.h>
#include <math.h>
#include <stdint.h>

// Problem constants
#define BB     4
#define CIN    256
#define HS     64
#define SFULL  512
#define CC     8
#define SMDIM  128
#define KP     4
#define PP     8
#define LL     256          // K of matmul
#define QQ     4096         // M total per (b,c)
#define PSQ    64           // N of matmul
#define OUT_ELEMS  (BB*CC*SFULL*SFULL)

// -------- scratch (device globals) --------
__device__ float g_y64[BB*CC*HS*HS];
__device__ __nv_bfloat16 g_Ub[BB*CC*PSQ*LL];            // [bc][p=64][k=256] bf16

__device__ __forceinline__ uint32_t smem_u32(const void* p) {
    uint32_t a;
    asm("{ .reg .u64 t; cvta.to.shared.u64 t, %1; cvt.u32.u64 %0, t; }"
        : "=r"(a) : "l"(p));
    return a;
}
#define CP16(dst_u32, src) \
    asm volatile("cp.async.cg.shared.global [%0], [%1], 16;" \
                 :: "r"(dst_u32), "l"(src))
#define CP_COMMIT() asm volatile("cp.async.commit_group;")
#define CP_WAIT1()  asm volatile("cp.async.wait_group 1;")

// ================= Kernel A: 1x1 conv (256 -> 8), 32px x 8 ic-split =================
// Reduction via store+reduce (NO smem atomics — ATOMS was the real bottleneck).
__global__ void __launch_bounds__(256)
conv1x1_kernel(const float* __restrict__ x,
               const float* __restrict__ w,
               const float* __restrict__ b) {
    __shared__ float ws[CC*CIN];
    __shared__ float part[8][32][9];       // [icq][px][c], pad 9 -> conflict-free
    int tid = threadIdx.x;
    for (int i = tid; i < CC*CIN; i += 256) ws[i] = w[i];
    __syncthreads();

    int px  = tid & 31;
    int icq = tid >> 5;                    // 0..7, 32 ic each
    int pid = blockIdx.x*32 + px;
    int bb  = pid >> 12;
    int p   = pid & 4095;

    const float* xp = x + (size_t)bb*CIN*HS*HS + (size_t)icq*32*HS*HS + p;

    float xv[32];
#pragma unroll
    for (int j = 0; j < 32; ++j)
        xv[j] = xp[(size_t)j*HS*HS];

    float acc[CC];
#pragma unroll
    for (int c = 0; c < CC; ++c) acc[c] = 0.f;
#pragma unroll
    for (int j = 0; j < 32; ++j) {
        int icg = icq*32 + j;
#pragma unroll
        for (int c = 0; c < CC; ++c) acc[c] += xv[j] * ws[c*CIN + icg];
    }
#pragma unroll
    for (int c = 0; c < CC; ++c) part[icq][px][c] = acc[c];
    __syncthreads();

    // reduce: warp = one class, lanes = px (coalesced g_y64 writes)
    {
        int c   = tid >> 5;                // 0..7
        int px2 = tid & 31;
        float s = b[c];
#pragma unroll
        for (int q = 0; q < 8; ++q) s += part[q][px2][c];
        int pid2 = blockIdx.x*32 + px2;
        int bb2  = pid2 >> 12;
        int p2   = pid2 & 4095;
        g_y64[(bb2*CC + c)*HS*HS + p2] = s;
    }
}

// ========= Kernel B: bilinear->argmax->4x4 pool -> unfold (bf16, [p][k]) =========
__global__ void argmax_pool_kernel() {
    int idx = blockIdx.x * blockDim.x + threadIdx.x;
    if (idx >= BB*SMDIM*SMDIM) return;
    int bb = idx >> 14;
    int r  = idx & 16383;
    int u  = r >> 7;
    int v  = r & 127;

    const double sc = 63.0 / 511.0;
    int cnt[CC];
#pragma unroll
    for (int c = 0; c < CC; ++c) cnt[c] = 0;

    const float* yb = g_y64 + bb*CC*HS*HS;

#pragma unroll
    for (int i = 0; i < KP; ++i) {
        int s = u*KP + i;
        float ps = (float)(s * sc);
        int lo_s = (int)ps; if (lo_s > 63) lo_s = 63;
        float wsv = ps - (float)lo_s;
        int hi_s = lo_s + 1; if (hi_s > 63) hi_s = 63;
#pragma unroll
        for (int j = 0; j < KP; ++j) {
            int t = v*KP + j;
            float pt = (float)(t * sc);
            int lo_t = (int)pt; if (lo_t > 63) lo_t = 63;
            float wtv = pt - (float)lo_t;
            int hi_t = lo_t + 1; if (hi_t > 63) hi_t = 63;

            float w00 = (1.f-wsv)*(1.f-wtv);
            float w01 = (1.f-wsv)*wtv;
            float w10 = wsv*(1.f-wtv);
            float w11 = wsv*wtv;

            float best = -3.4e38f;
            int bi = 0;
#pragma unroll
            for (int c = 0; c < CC; ++c) {
                const float* yc = yb + c*HS*HS;
                float yv = w00*yc[lo_s*HS + lo_t] + w01*yc[lo_s*HS + hi_t]
                         + w10*yc[hi_s*HS + lo_t] + w11*yc[hi_s*HS + hi_t];
                if (yv > best) { best = yv; bi = c; }
            }
            cnt[bi]++;
        }
    }

    int p = ((u & 7) << 3) | (v & 7);
    int l = ((u >> 3) << 4) | (v >> 3);
#pragma unroll
    for (int c = 0; c < CC; ++c)
        g_Ub[((bb*CC + c)*PSQ + p)*LL + l] =
            __float2bfloat16((float)cnt[c] * 0.0625f);
}

// ====== Kernel D: fused GEMM(8 classes) + nz + passthrough + softmax, cp.async pipelined ======
#define ALD 264
#define OFF_AS    0
#define OFF_BS    16896                    // 32*ALD*2
#define OFF_STAGE 50688                    // + 64*ALD*2
#define OFF_YROW  83456                    // + 2*16*256*4
#define FUSED_SMEM 99840                   // + 4096*4

__global__ void __launch_bounds__(256, 2)
fused_kernel(const float* __restrict__ attn, float* __restrict__ out,
             float* __restrict__ attn_out) {
    extern __shared__ char dsm[];
    __nv_bfloat16* As = (__nv_bfloat16*)(dsm + OFF_AS);     // [32][ALD]
    __nv_bfloat16* Bs = (__nv_bfloat16*)(dsm + OFF_BS);     // [64][ALD]
    float* stagef     = (float*)(dsm + OFF_STAGE);          // [2][16*256]
    float* yrow       = (float*)(dsm + OFF_YROW);           // [8c][8sr][64]
    __shared__ int cnts[CC][32][2];        // [class][row][warp-parity], no atomics

    const int tid  = threadIdx.x;
    const int wid  = tid >> 5, lane = tid & 31;
    const int g    = lane >> 2, tg = lane & 3;
    const int wr   = wid & 1,  wc  = wid >> 1;
    const int wp   = wid & 1;              // warp parity (row co-writer id)
    const int mrow = wr * 16;
    const int mt   = blockIdx.x;
    const int b    = blockIdx.y;
    const int m0   = mt * 32;
    const int sh0  = (mt >> 1) * 8;
    const double sc = 63.0 / 511.0;

    const uint32_t stage_u32 = smem_u32(stagef);
    const uint32_t bs_u32    = smem_u32(Bs);

    // ---- prologue: G0 = A(c0,h0)+B(c0); G1 = A(c0,h1) ----
    {
        const char* a0 = (const char*)(attn + ((size_t)(b*CC+0)*QQ + m0)*LL);
        const char* bsrc = (const char*)(g_Ub + (size_t)(b*CC+0)*PSQ*LL);
#pragma unroll
        for (int i = 0; i < 4; ++i) {
            int ch = i*256 + tid;
            CP16(stage_u32 + ch*16, a0 + ch*16);
        }
#pragma unroll
        for (int i = 0; i < 8; ++i) {
            int ch = i*256 + tid;
            CP16(bs_u32 + (ch >> 5)*528 + (ch & 31)*16, bsrc + ch*16);
        }
        CP_COMMIT();
#pragma unroll
        for (int i = 0; i < 4; ++i) {
            int ch = i*256 + tid;
            CP16(stage_u32 + 16384 + ch*16, a0 + 16384 + ch*16);
        }
        CP_COMMIT();
    }

    // ---- yrow precompute (overlaps prologue cp.async latency) ----
#pragma unroll
    for (int it = 0; it < 16; ++it) {
        int i   = it*256 + tid;
        int c   = i >> 9;
        int sr  = (i >> 6) & 7;
        int col = i & 63;
        int s   = sh0 + sr;
        float ps = (float)(s * sc);
        int ls = (int)ps; if (ls > 63) ls = 63;
        float wsv = ps - (float)ls;
        int hs = ls + 1; if (hs > 63) hs = 63;
        const float* yc = g_y64 + (b*CC + c)*HS*HS;
        float lo = yc[ls*HS + col], hi = yc[hs*HS + col];
        yrow[i] = lo + wsv*(hi - lo);
    }

    float corr[CC][2][4];
#pragma unroll
    for (int c = 0; c < CC; ++c)
#pragma unroll
        for (int j = 0; j < 2; ++j)
#pragma unroll
            for (int i = 0; i < 4; ++i) corr[c][j][i] = 0.f;

    // ---- pipelined stage loop: 16 stages = 8 classes x 2 half-tiles ----
#pragma unroll
    for (int s = 0; s < 16; ++s) {
        const int c = s >> 1, h = s & 1;
        const int bc = b*CC + c;

        CP_WAIT1();
        __syncthreads();                   // stage s data visible; prev readers done

        // process stage s: passthrough (.cs) + nz + bf16 -> As
        float4* Og  = (float4*)(attn_out + ((size_t)bc*QQ + m0)*LL);
        const float4* buf = (const float4*)(stagef + (s & 1)*4096);
#pragma unroll
        for (int i = 0; i < 4; ++i) {
            int flat = i*256 + tid;        // float4 idx within half
            int row  = h*16 + (flat >> 6); // warp-uniform
            int k    = (flat & 63) << 2;
            float4 v = buf[flat];
            __stcs(&Og[h*1024 + flat], v);
            int cn = (v.x != 0.f) + (v.y != 0.f) + (v.z != 0.f) + (v.w != 0.f);
            cn = __reduce_add_sync(0xFFFFFFFFu, cn);
            if (lane == 0) cnts[c][row][wp] = cn;   // exactly one writer -> no atomic
            __nv_bfloat162 h0 = __floats2bfloat162_rn(v.x, v.y);
            __nv_bfloat162 h1 = __floats2bfloat162_rn(v.z, v.w);
            *(uint2*)(As + row*ALD + k) = make_uint2(*(uint32_t*)&h0, *(uint32_t*)&h1);
        }
        __syncthreads();                   // buf[s&1] free; As half + cnts done

        if (h == 0) {
            // prefetch stage s+2 = (class c+1, half0)
            if (s + 2 <= 15) {
                int c2 = (s+2) >> 1;
                const char* asrc = (const char*)(attn +
                    ((size_t)(b*CC+c2)*QQ + m0)*LL);
#pragma unroll
                for (int i = 0; i < 4; ++i) {
                    int ch = i*256 + tid;
                    CP16(stage_u32 + (s & 1)*16384 + ch*16, asrc + ch*16);
                }
            }
            CP_COMMIT();
        } else {
            // EARLY prefetch of A(c+1, half1): slot free, MMA gives latency cover.
            if (s + 2 <= 15) {
                int c2 = (s+2) >> 1;
                const char* asrc = (const char*)(attn +
                    ((size_t)(b*CC+c2)*QQ + m0 + 16)*LL);   // half1 rows
#pragma unroll
                for (int i = 0; i < 4; ++i) {
                    int ch = i*256 + tid;
                    CP16(stage_u32 + (s & 1)*16384 + ch*16, asrc + ch*16);
                }
            }
            CP_COMMIT();

            // per-thread row scales from the two parity slots (post-sync visible)
            float s0 = 1.f / ((float)(cnts[c][mrow + g][0] + cnts[c][mrow + g][1]) + 1e-5f);
            float s1 = 1.f / ((float)(cnts[c][mrow + g + 8][0] + cnts[c][mrow + g + 8][1]) + 1e-5f);

            // HMMA for class c
            const __nv_bfloat16* Ab = As + (mrow + g)*ALD + tg*2;
#pragma unroll 4
            for (int ks = 0; ks < 16; ++ks) {
                int kk = ks * 16;
                uint32_t a0 = *(const uint32_t*)(Ab + kk);
                uint32_t a1 = *(const uint32_t*)(Ab + 8*ALD + kk);
                uint32_t a2 = *(const uint32_t*)(Ab + kk + 8);
                uint32_t a3 = *(const uint32_t*)(Ab + 8*ALD + kk + 8);
#pragma unroll
                for (int j = 0; j < 2; ++j) {
                    const __nv_bfloat16* Bb = Bs + (wc*16 + j*8 + g)*ALD + kk + tg*2;
                    uint32_t b0 = *(const uint32_t*)(Bb);
                    uint32_t b1 = *(const uint32_t*)(Bb + 8);
                    asm volatile(
                        "mma.sync.aligned.m16n8k16.row.col.f32.bf16.bf16.f32 "
                        "{%0,%1,%2,%3}, {%4,%5,%6,%7}, {%8,%9}, {%0,%1,%2,%3};"
                        : "+f"(corr[c][j][0]), "+f"(corr[c][j][1]),
                          "+f"(corr[c][j][2]), "+f"(corr[c][j][3])
                        : "r"(a0), "r"(a1), "r"(a2), "r"(a3), "r"(b0), "r"(b1));
                }
            }
#pragma unroll
            for (int j = 0; j < 2; ++j) {
                corr[c][j][0] *= s0; corr[c][j][1] *= s0;
                corr[c][j][2] *= s1; corr[c][j][3] *= s1;
            }
            __syncthreads();               // all MMA reads of As/Bs done

            // B(c+1) prefetch (Bs single-buffered -> must follow MMA)
            if (s + 2 <= 15) {
                int c2 = (s+2) >> 1;
                const char* bsrc = (const char*)(g_Ub + (size_t)(b*CC+c2)*PSQ*LL);
#pragma unroll
                for (int i = 0; i < 8; ++i) {
                    int ch = i*256 + tid;
                    CP16(bs_u32 + (ch >> 5)*528 + (ch & 31)*16, bsrc + ch*16);
                }
            }
            CP_COMMIT();
        }
    }

    // ---- fused epilogue: (corr+1)*y, log_softmax, write out (.cs) ----
#pragma unroll
    for (int r = 0; r < 2; ++r) {
        int qrow = mrow + g + r*8;
        int q    = m0 + qrow;
        int t0   = ((q & 63) << 3) + tg*2;
        int t1   = t0 + 1;
        float pt0 = (float)(t0 * sc);
        int lt0 = (int)pt0; if (lt0 > 63) lt0 = 63;
        float wt0 = pt0 - (float)lt0;
        int ht0 = lt0 + 1; if (ht0 > 63) ht0 = 63;
        float pt1 = (float)(t1 * sc);
        int lt1 = (int)pt1; if (lt1 > 63) lt1 = 63;
        float wt1 = pt1 - (float)lt1;
        int ht1 = lt1 + 1; if (ht1 > 63) ht1 = 63;

#pragma unroll
        for (int j = 0; j < 2; ++j) {
            int sr = wc*2 + j;
            float v0[CC], v1[CC];
            float m0v = -3.4e38f, m1v = -3.4e38f;
#pragma unroll
            for (int c = 0; c < CC; ++c) {
                const float* yr = yrow + (c*8 + sr)*64;
                float a0 = yr[lt0];
                float y0 = a0 + wt0*(yr[ht0] - a0);
                float a1 = yr[lt1];
                float y1 = a1 + wt1*(yr[ht1] - a1);
                v0[c] = (corr[c][j][r*2+0] + 1.f) * y0;
                v1[c] = (corr[c][j][r*2+1] + 1.f) * y1;
                m0v = fmaxf(m0v, v0[c]);
                m1v = fmaxf(m1v, v1[c]);
            }
            float su0 = 0.f, su1 = 0.f;
#pragma unroll
            for (int c = 0; c < CC; ++c) {
                su0 += __expf(v0[c] - m0v);
                su1 += __expf(v1[c] - m1v);
            }
            float lse0 = logf(su0) + m0v;
            float lse1 = logf(su1) + m1v;
            int s_glob = sh0 + sr;
#pragma unroll
            for (int c = 0; c < CC; ++c) {
                float* op = out + (((size_t)(b*CC + c)) << 18) + (s_glob << 9) + t0;
                __stcs((float2*)op, make_float2(v0[c] - lse0, v1[c] - lse1));
            }
        }
    }
}

// ======================= launch =======================
extern "C" void kernel_launch(void* const* d_in, const int* in_sizes, int n_in,
                              void* d_out, int out_size) {
    const float* x    = (const float*)d_in[0];
    const float* attn = (const float*)d_in[1];
    const float* cw   = (const float*)d_in[2];
    const float* cb   = (const float*)d_in[3];
    float* out = (float*)d_out;

    conv1x1_kernel<<<BB*HS*HS/32, 256>>>(x, cw, cb);
    argmax_pool_kernel<<<(BB*SMDIM*SMDIM + 255)/256, 256>>>();

    static int smem_set = 0;
    if (!smem_set) {
        cudaFuncSetAttribute(fused_kernel,
                             cudaFuncAttributeMaxDynamicSharedMemorySize,
                             FUSED_SMEM);
        smem_set = 1;
    }
    fused_kernel<<<dim3(QQ/32, BB), 256, FUSED_SMEM>>>(attn, out, out + OUT_ELEMS);
}